// round 13
// baseline (speedup 1.0000x reference)
#include <cuda_runtime.h>
#include <cuda_fp16.h>

#define S_LEN 2048
#define NHEAD 16
#define DHEAD 64
#define BM 128
#define BN 64
#define KSTRH 72    // halves; 144B row stride -> conflict-free LDS.128
#define VTSTRH 72
#define BUF_HALVES (BN * KSTRH + DHEAD * VTSTRH)   // 9216

#define QSCALE 0.18033688011112042f    /* 0.125 * log2(e) */
#define MASKVAL (-14426.950408889634f) /* -10000 * log2(e) */

// fp16 scratch — __device__ globals, no allocation.
// g_Kh rows are d-permuted: pos = 16*((d>>2)&3) + 4*(d>>4) + (d&3)
// g_Vt is [bh][d][key-pos], key-pos doubly permuted (R11 perm + LDS.128 repack)
__device__ __half g_Kh[(size_t)4 * NHEAD * S_LEN * DHEAD];
__device__ __half g_Vt[(size_t)4 * NHEAD * DHEAD * S_LEN];

static __device__ __forceinline__ unsigned packh2(float lo, float hi) {
    __half2 h = __floats2half2_rn(lo, hi);
    return *(unsigned*)&h;
}

static __device__ __forceinline__ float ex2(float x) {
    float y;
    asm("ex2.approx.ftz.f32 %0, %1;" : "=f"(y) : "f"(x));
    return y;
}

static __device__ __forceinline__ void mma_f16(float* d,
                                               unsigned a0, unsigned a1, unsigned a2, unsigned a3,
                                               unsigned b0, unsigned b1) {
    asm volatile("mma.sync.aligned.m16n8k16.row.col.f32.f16.f16.f32 "
                 "{%0,%1,%2,%3}, {%4,%5,%6,%7}, {%8,%9}, {%0,%1,%2,%3};"
                 : "+f"(d[0]), "+f"(d[1]), "+f"(d[2]), "+f"(d[3])
                 : "r"(a0), "r"(a1), "r"(a2), "r"(a3), "r"(b0), "r"(b1));
}

#define CP_ASYNC16(dst_u32, src_ptr) \
    asm volatile("cp.async.cg.shared.global [%0], [%1], 16;" :: "r"(dst_u32), "l"(src_ptr))
#define CP_COMMIT() asm volatile("cp.async.commit_group;" ::: "memory")
#define CP_WAIT0()  asm volatile("cp.async.wait_group 0;" ::: "memory")

// ---- Pre-pass: K -> fp16 row-permuted; V -> fp16 transposed + key-permuted ----
__global__ __launch_bounds__(128)
void prep_kernel(const float* __restrict__ K, const float* __restrict__ V) {
    const int kt  = blockIdx.x;
    const int bh  = blockIdx.y;
    const int tid = threadIdx.x;

    const float* Kg = K + ((size_t)bh * S_LEN + (size_t)kt * 64) * DHEAD;
    const float* Vg = V + ((size_t)bh * S_LEN + (size_t)kt * 64) * DHEAD;
    __half* Kh = g_Kh + ((size_t)bh * S_LEN + (size_t)kt * 64) * DHEAD;

    #pragma unroll
    for (int it = 0; it < 8; it++) {
        int i  = tid + (it << 7);
        int r  = i >> 4;
        int d4 = (i & 15) << 2;
        float4 kk = *(const float4*)(Kg + r * DHEAD + d4);
        int p = 16 * ((d4 >> 2) & 3) + 4 * (d4 >> 4);   // LDS.128 repack
        __half2* dst = (__half2*)(Kh + r * DHEAD + p);
        dst[0] = __floats2half2_rn(kk.x, kk.y);
        dst[1] = __floats2half2_rn(kk.z, kk.w);
    }

    const int v_rp = tid & 15;
    const int v_h  = tid >> 4;
    #pragma unroll
    for (int u = 0; u < 2; u++)
        #pragma unroll
        for (int kh = 0; kh < 2; kh++) {
            int key = 2 * (v_rp + 16 * kh);
            int w   = key & 15;
            int q   = (key & ~15) + 4 * ((w & 7) >> 1) + ((w < 8) ? 0 : 2);  // R11 perm
            int pos = 16 * ((q >> 2) & 3) + 4 * (q >> 4) + (q & 3);          // LDS.128 repack
            int dv  = 4 * v_h + 32 * u;
            const float* vp = Vg + key * DHEAD + dv;
            float4 v0 = *(const float4*)vp;
            float4 v1 = *(const float4*)(vp + DHEAD);
            __half* Vt = g_Vt + (size_t)bh * DHEAD * S_LEN + (size_t)kt * 64 + pos;
            *(__half2*)(Vt + (size_t)(dv + 0) * S_LEN) = __floats2half2_rn(v0.x, v1.x);
            *(__half2*)(Vt + (size_t)(dv + 1) * S_LEN) = __floats2half2_rn(v0.y, v1.y);
            *(__half2*)(Vt + (size_t)(dv + 2) * S_LEN) = __floats2half2_rn(v0.z, v1.z);
            *(__half2*)(Vt + (size_t)(dv + 3) * S_LEN) = __floats2half2_rn(v0.w, v1.w);
        }
}

__global__ __launch_bounds__(128, 3)
void attn_tc9_kernel(const float* __restrict__ Q, float* __restrict__ Out) {
    extern __shared__ __half smh[];
    const unsigned smem_b = (unsigned)__cvta_generic_to_shared(smh);

    const int qt   = (gridDim.x - 1) - blockIdx.x;   // heavy tiles first
    const int bh   = blockIdx.y;
    const int b    = bh >> 4;
    const int h    = bh & 15;
    const int qrow = qt * BM;

    const int tid   = threadIdx.x;
    const int warp  = tid >> 5;
    const int lane  = tid & 31;
    const int g     = lane >> 2;
    const int t4    = lane & 3;
    const int wbase = qrow + (warp << 5);   // 32 rows per warp: slab0 +0..15, slab1 +16..31

    const char* KhB = (const char*)(g_Kh + (size_t)bh * S_LEN * DHEAD);
    const char* VtB = (const char*)(g_Vt + (size_t)bh * DHEAD * S_LEN);

    // ---- Q A-fragments (fp16, pre-scaled), both slabs ----
    unsigned qa[2][4][4];
    {
        #pragma unroll
        for (int sl = 0; sl < 2; sl++) {
            const float* Qg = Q + ((size_t)bh * S_LEN + wbase + 16 * sl) * DHEAD;
            #pragma unroll
            for (int ks = 0; ks < 4; ks++) {
                const float* rp = Qg + g * DHEAD + 16 * ks + 4 * t4;
                float4 x = *(const float4*)rp;
                float4 y = *(const float4*)(rp + 8 * DHEAD);
                qa[sl][ks][0] = packh2(QSCALE * x.x, QSCALE * x.y);
                qa[sl][ks][1] = packh2(QSCALE * y.x, QSCALE * y.y);
                qa[sl][ks][2] = packh2(QSCALE * x.z, QSCALE * x.w);
                qa[sl][ks][3] = packh2(QSCALE * y.z, QSCALE * y.w);
            }
        }
    }

    float o0[8][4], o1[8][4];
    #pragma unroll
    for (int nt = 0; nt < 8; nt++)
        #pragma unroll
        for (int e = 0; e < 4; e++) { o0[nt][e] = 0.f; o1[nt][e] = 0.f; }

    float m[2][2], l[2][2];
    m[0][0] = m[0][1] = m[1][0] = m[1][1] = -1e30f;
    l[0][0] = l[0][1] = l[1][0] = l[1][1] = 0.f;

    auto stage = [&](int kt, int slot) {
        unsigned sb = smem_b + (unsigned)slot * (BUF_HALVES * 2);
        const char* Ksrc = KhB + (size_t)kt * BN * DHEAD * 2;
        #pragma unroll
        for (int it = 0; it < 4; it++) {
            int c = tid + (it << 7);
            unsigned dst = sb + (unsigned)(c >> 3) * (KSTRH * 2) + (unsigned)(c & 7) * 16;
            CP_ASYNC16(dst, Ksrc + (size_t)c * 16);
        }
        const char* Vsrc = VtB + (size_t)kt * BN * 2;
        unsigned vb = sb + BN * KSTRH * 2;
        #pragma unroll
        for (int it = 0; it < 4; it++) {
            int c = tid + (it << 7);
            int r = c >> 3;
            unsigned dst = vb + (unsigned)r * (VTSTRH * 2) + (unsigned)(c & 7) * 16;
            CP_ASYNC16(dst, Vsrc + (size_t)r * (S_LEN * 2) + (size_t)(c & 7) * 16);
        }
        CP_COMMIT();
    };

    stage(0, 0);
    const int kt_last = 2 * qt + 1;

    // GEMM1 + softmax for one slab (s reused across slabs)
    unsigned ph0[8][2], ph1[8][2];
    auto do_slab = [&](int sl, const __half* Kc, float (&oo)[8][4],
                       unsigned (&ph)[8][2], bool diag, int colb) {
        float s[8][4];
        #pragma unroll
        for (int nt = 0; nt < 8; nt++) {
            s[nt][0] = 0.f; s[nt][1] = 0.f; s[nt][2] = 0.f; s[nt][3] = 0.f;
            const __half* kb = Kc + (g + 8 * nt) * KSTRH + 16 * t4;
            uint4 lo = *(const uint4*)kb;
            uint4 hi = *(const uint4*)(kb + 8);
            mma_f16(s[nt], qa[sl][0][0], qa[sl][0][1], qa[sl][0][2], qa[sl][0][3], lo.x, lo.y);
            mma_f16(s[nt], qa[sl][1][0], qa[sl][1][1], qa[sl][1][2], qa[sl][1][3], lo.z, lo.w);
            mma_f16(s[nt], qa[sl][2][0], qa[sl][2][1], qa[sl][2][2], qa[sl][2][3], hi.x, hi.y);
            mma_f16(s[nt], qa[sl][3][0], qa[sl][3][1], qa[sl][3][2], qa[sl][3][3], hi.z, hi.w);
        }

        const int rowA = wbase + 16 * sl + g;
        const int rowB = rowA + 8;
        if (diag) {
            #pragma unroll
            for (int nt = 0; nt < 8; nt++) {
                int c0 = colb + 8 * nt, c1 = c0 + 1;
                if (c0 > rowA) s[nt][0] = MASKVAL;
                if (c1 > rowA) s[nt][1] = MASKVAL;
                if (c0 > rowB) s[nt][2] = MASKVAL;
                if (c1 > rowB) s[nt][3] = MASKVAL;
            }
        }

        float a0r[8], a1r[8];
        #pragma unroll
        for (int nt = 0; nt < 8; nt++) {
            a0r[nt] = fmaxf(s[nt][0], s[nt][1]);
            a1r[nt] = fmaxf(s[nt][2], s[nt][3]);
        }
        #pragma unroll
        for (int st = 4; st >= 1; st >>= 1)
            #pragma unroll
            for (int i = 0; i < st; i++) {
                a0r[i] = fmaxf(a0r[i], a0r[i + st]);
                a1r[i] = fmaxf(a1r[i], a1r[i + st]);
            }
        float mx0 = a0r[0], mx1 = a1r[0];
        mx0 = fmaxf(mx0, __shfl_xor_sync(0xffffffffu, mx0, 1));
        mx0 = fmaxf(mx0, __shfl_xor_sync(0xffffffffu, mx0, 2));
        mx1 = fmaxf(mx1, __shfl_xor_sync(0xffffffffu, mx1, 1));
        mx1 = fmaxf(mx1, __shfl_xor_sync(0xffffffffu, mx1, 2));

        float mn0 = fmaxf(m[sl][0], mx0), mn1 = fmaxf(m[sl][1], mx1);
        float cr0 = ex2(m[sl][0] - mn0), cr1 = ex2(m[sl][1] - mn1);

        #pragma unroll
        for (int nt = 0; nt < 8; nt++) {
            float p0 = ex2(s[nt][0] - mn0);
            float p1 = ex2(s[nt][1] - mn0);
            float p2 = ex2(s[nt][2] - mn1);
            float p3 = ex2(s[nt][3] - mn1);
            a0r[nt] = p0 + p1;
            a1r[nt] = p2 + p3;
            ph[nt][0] = packh2(p0, p1);
            ph[nt][1] = packh2(p2, p3);
        }
        #pragma unroll
        for (int st = 4; st >= 1; st >>= 1)
            #pragma unroll
            for (int i = 0; i < st; i++) {
                a0r[i] += a0r[i + st];
                a1r[i] += a1r[i + st];
            }
        float sum0 = a0r[0], sum1 = a1r[0];
        sum0 += __shfl_xor_sync(0xffffffffu, sum0, 1);
        sum0 += __shfl_xor_sync(0xffffffffu, sum0, 2);
        sum1 += __shfl_xor_sync(0xffffffffu, sum1, 1);
        sum1 += __shfl_xor_sync(0xffffffffu, sum1, 2);

        l[sl][0] = l[sl][0] * cr0 + sum0;
        l[sl][1] = l[sl][1] * cr1 + sum1;
        m[sl][0] = mn0; m[sl][1] = mn1;

        #pragma unroll
        for (int nt = 0; nt < 8; nt++) {
            oo[nt][0] *= cr0; oo[nt][1] *= cr0;
            oo[nt][2] *= cr1; oo[nt][3] *= cr1;
        }
    };

    for (int kt = 0; kt <= kt_last; kt++) {
        const int cur = kt & 1;
        const __half* Kc = smh + cur * BUF_HALVES;
        const __half* Vc = Kc + BN * KSTRH;

        CP_WAIT0();
        __syncthreads();

        if (kt < kt_last) stage(kt + 1, cur ^ 1);

        // tile entirely above this warp's rows -> no compute (staging/barrier already done)
        if ((kt << 6) > wbase + 31) continue;

        const bool diag = ((kt << 6) + 63 > wbase);
        const int  colb = (kt << 6) + 2 * t4;

        do_slab(0, Kc, o0, ph0, diag, colb);
        do_slab(1, Kc, o1, ph1, diag, colb);

        // ---- GEMM2: B-frags loaded once, shared by both slabs ----
        #pragma unroll
        for (int nt = 0; nt < 8; nt++) {
            const __half* vp = Vc + (g + 8 * nt) * VTSTRH + 16 * t4;
            uint4 lo = *(const uint4*)vp;
            uint4 hi = *(const uint4*)(vp + 8);
            mma_f16(o0[nt], ph0[0][0], ph0[0][1], ph0[1][0], ph0[1][1], lo.x, lo.y);
            mma_f16(o0[nt], ph0[2][0], ph0[2][1], ph0[3][0], ph0[3][1], lo.z, lo.w);
            mma_f16(o0[nt], ph0[4][0], ph0[4][1], ph0[5][0], ph0[5][1], hi.x, hi.y);
            mma_f16(o0[nt], ph0[6][0], ph0[6][1], ph0[7][0], ph0[7][1], hi.z, hi.w);
            mma_f16(o1[nt], ph1[0][0], ph1[0][1], ph1[1][0], ph1[1][1], lo.x, lo.y);
            mma_f16(o1[nt], ph1[2][0], ph1[2][1], ph1[3][0], ph1[3][1], lo.z, lo.w);
            mma_f16(o1[nt], ph1[4][0], ph1[4][1], ph1[5][0], ph1[5][1], hi.x, hi.y);
            mma_f16(o1[nt], ph1[6][0], ph1[6][1], ph1[7][0], ph1[7][1], hi.z, hi.w);
        }
    }

    // ---- Epilogue: 4 rows per thread ----
    #pragma unroll
    for (int sl = 0; sl < 2; sl++) {
        float (*oo)[4] = sl ? o1 : o0;
        const float invA = 1.f / l[sl][0];
        const float invB = 1.f / l[sl][1];
        const int rowA = wbase + 16 * sl + g;
        float* OpA = Out + ((size_t)b * S_LEN + rowA)     * (NHEAD * DHEAD) + h * DHEAD;
        float* OpB = Out + ((size_t)b * S_LEN + rowA + 8) * (NHEAD * DHEAD) + h * DHEAD;
        #pragma unroll
        for (int nt = 0; nt < 8; nt++) {
            int col = 8 * nt + 2 * t4;
            *(float2*)(OpA + col) = make_float2(oo[nt][0] * invA, oo[nt][1] * invA);
            *(float2*)(OpB + col) = make_float2(oo[nt][2] * invB, oo[nt][3] * invB);
        }
    }
}

extern "C" void kernel_launch(void* const* d_in, const int* in_sizes, int n_in,
                              void* d_out, int out_size) {
    (void)in_sizes; (void)n_in; (void)out_size;
    const float* q = (const float*)d_in[0];
    const float* k = (const float*)d_in[1];
    const float* v = (const float*)d_in[2];
    float* out = (float*)d_out;

    dim3 pgrid(S_LEN / 64, 4 * NHEAD);
    prep_kernel<<<pgrid, 128>>>(k, v);

    const int smem_bytes = 2 * BUF_HALVES * (int)sizeof(__half);   // 36864 B
    cudaFuncSetAttribute(attn_tc9_kernel,
                         cudaFuncAttributeMaxDynamicSharedMemorySize, smem_bytes);
    dim3 grid(S_LEN / BM, 4 * NHEAD);   // (16, 64)
    attn_tc9_kernel<<<grid, 128, smem_bytes>>>(q, out);
}

// round 14
// speedup vs baseline: 1.0231x; 1.0231x over previous
#include <cuda_runtime.h>
#include <cuda_fp16.h>

#define S_LEN 2048
#define NHEAD 16
#define DHEAD 64
#define BM 64
#define BN 64
#define KSTRH 72    // halves; 144B row stride -> conflict-free LDS.128
#define VTSTRH 72
#define BUF_HALVES (BN * KSTRH + DHEAD * VTSTRH)   // 9216

#define QSCALE 0.18033688011112042f    /* 0.125 * log2(e) */
#define MASKVAL (-14426.950408889634f) /* -10000 * log2(e) */

// fp16 scratch — __device__ globals, no allocation.
// g_Kh rows are d-permuted: chunk d4 -> pos 16*((d4>>2)&3) + 4*(d4>>4)
// g_Vt is [bh][d][key-pos], key-pos doubly permuted (R11 perm + LDS.128 repack)
__device__ __half g_Kh[(size_t)4 * NHEAD * S_LEN * DHEAD];
__device__ __half g_Vt[(size_t)4 * NHEAD * DHEAD * S_LEN];

static __device__ __forceinline__ unsigned packh2(float lo, float hi) {
    __half2 h = __floats2half2_rn(lo, hi);
    return *(unsigned*)&h;
}

static __device__ __forceinline__ float ex2(float x) {
    float y;
    asm("ex2.approx.ftz.f32 %0, %1;" : "=f"(y) : "f"(x));
    return y;
}

static __device__ __forceinline__ void mma_f16(float* d,
                                               unsigned a0, unsigned a1, unsigned a2, unsigned a3,
                                               unsigned b0, unsigned b1) {
    asm volatile("mma.sync.aligned.m16n8k16.row.col.f32.f16.f16.f32 "
                 "{%0,%1,%2,%3}, {%4,%5,%6,%7}, {%8,%9}, {%0,%1,%2,%3};"
                 : "+f"(d[0]), "+f"(d[1]), "+f"(d[2]), "+f"(d[3])
                 : "r"(a0), "r"(a1), "r"(a2), "r"(a3), "r"(b0), "r"(b1));
}

#define CP_ASYNC16(dst_u32, src_ptr) \
    asm volatile("cp.async.cg.shared.global [%0], [%1], 16;" :: "r"(dst_u32), "l"(src_ptr))
#define CP_COMMIT() asm volatile("cp.async.commit_group;" ::: "memory")
#define CP_WAIT0()  asm volatile("cp.async.wait_group 0;" ::: "memory")

// ---- Pre-pass: K -> fp16 row-permuted; V -> fp16 transposed + key-permuted ----
__global__ __launch_bounds__(128)
void prep_kernel(const float* __restrict__ K, const float* __restrict__ V) {
    const int kt  = blockIdx.x;
    const int bh  = blockIdx.y;
    const int tid = threadIdx.x;

    const float* Kg = K + ((size_t)bh * S_LEN + (size_t)kt * 64) * DHEAD;
    const float* Vg = V + ((size_t)bh * S_LEN + (size_t)kt * 64) * DHEAD;
    __half* Kh = g_Kh + ((size_t)bh * S_LEN + (size_t)kt * 64) * DHEAD;

    #pragma unroll
    for (int it = 0; it < 8; it++) {
        int i  = tid + (it << 7);
        int r  = i >> 4;
        int d4 = (i & 15) << 2;
        float4 kk = *(const float4*)(Kg + r * DHEAD + d4);
        int p = 16 * ((d4 >> 2) & 3) + 4 * (d4 >> 4);   // LDS.128 repack
        __half2* dst = (__half2*)(Kh + r * DHEAD + p);
        dst[0] = __floats2half2_rn(kk.x, kk.y);
        dst[1] = __floats2half2_rn(kk.z, kk.w);
    }

    const int v_rp = tid & 15;
    const int v_h  = tid >> 4;
    #pragma unroll
    for (int u = 0; u < 2; u++)
        #pragma unroll
        for (int kh = 0; kh < 2; kh++) {
            int key = 2 * (v_rp + 16 * kh);
            int w   = key & 15;
            int q   = (key & ~15) + 4 * ((w & 7) >> 1) + ((w < 8) ? 0 : 2);  // R11 perm
            int pos = 16 * ((q >> 2) & 3) + 4 * (q >> 4) + (q & 3);          // LDS.128 repack
            int dv  = 4 * v_h + 32 * u;
            const float* vp = Vg + key * DHEAD + dv;
            float4 v0 = *(const float4*)vp;
            float4 v1 = *(const float4*)(vp + DHEAD);
            __half* Vt = g_Vt + (size_t)bh * DHEAD * S_LEN + (size_t)kt * 64 + pos;
            *(__half2*)(Vt + (size_t)(dv + 0) * S_LEN) = __floats2half2_rn(v0.x, v1.x);
            *(__half2*)(Vt + (size_t)(dv + 1) * S_LEN) = __floats2half2_rn(v0.y, v1.y);
            *(__half2*)(Vt + (size_t)(dv + 2) * S_LEN) = __floats2half2_rn(v0.z, v1.z);
            *(__half2*)(Vt + (size_t)(dv + 3) * S_LEN) = __floats2half2_rn(v0.w, v1.w);
        }
}

__global__ __launch_bounds__(128, 5)
void attn_tc10_kernel(const float* __restrict__ Q, float* __restrict__ Out) {
    extern __shared__ __half smh[];
    const unsigned smem_b = (unsigned)__cvta_generic_to_shared(smh);

    const int qt   = (gridDim.x - 1) - blockIdx.x;   // heavy tiles first
    const int bh   = blockIdx.y;
    const int b    = bh >> 4;
    const int h    = bh & 15;
    const int qrow = qt * BM;

    const int tid  = threadIdx.x;
    const int warp = tid >> 5;
    const int lane = tid & 31;
    const int g    = lane >> 2;
    const int t4   = lane & 3;
    const int r0w  = warp << 4;
    const int row0 = qrow + r0w + g;
    const int row1 = row0 + 8;

    const char* KhB = (const char*)(g_Kh + (size_t)bh * S_LEN * DHEAD);
    const char* VtB = (const char*)(g_Vt + (size_t)bh * DHEAD * S_LEN);

    // ---- Q A-fragments (fp16, pre-scaled). k-map matches repacked K rows. ----
    unsigned qa[4][4];
    {
        const float* Qg = Q + ((size_t)bh * S_LEN + qrow + r0w) * DHEAD;
        #pragma unroll
        for (int ks = 0; ks < 4; ks++) {
            const float* rp = Qg + g * DHEAD + 16 * ks + 4 * t4;
            float4 x = *(const float4*)rp;
            float4 y = *(const float4*)(rp + 8 * DHEAD);
            qa[ks][0] = packh2(QSCALE * x.x, QSCALE * x.y);
            qa[ks][1] = packh2(QSCALE * y.x, QSCALE * y.y);
            qa[ks][2] = packh2(QSCALE * x.z, QSCALE * x.w);
            qa[ks][3] = packh2(QSCALE * y.z, QSCALE * y.w);
        }
    }

    float o[8][4];
    #pragma unroll
    for (int nt = 0; nt < 8; nt++)
        #pragma unroll
        for (int e = 0; e < 4; e++) o[nt][e] = 0.f;

    float m0 = -1e30f, m1 = -1e30f, l0 = 0.f, l1 = 0.f;

    auto stage = [&](int kt, int slot) {
        unsigned sb = smem_b + (unsigned)slot * (BUF_HALVES * 2);
        const char* Ksrc = KhB + (size_t)kt * BN * DHEAD * 2;
        #pragma unroll
        for (int it = 0; it < 4; it++) {
            int c = tid + (it << 7);
            unsigned dst = sb + (unsigned)(c >> 3) * (KSTRH * 2) + (unsigned)(c & 7) * 16;
            CP_ASYNC16(dst, Ksrc + (size_t)c * 16);
        }
        const char* Vsrc = VtB + (size_t)kt * BN * 2;
        unsigned vb = sb + BN * KSTRH * 2;
        #pragma unroll
        for (int it = 0; it < 4; it++) {
            int c = tid + (it << 7);
            int r = c >> 3;
            unsigned dst = vb + (unsigned)r * (VTSTRH * 2) + (unsigned)(c & 7) * 16;
            CP_ASYNC16(dst, Vsrc + (size_t)r * (S_LEN * 2) + (size_t)(c & 7) * 16);
        }
        CP_COMMIT();
    };

    stage(0, 0);

    for (int kt = 0; kt <= qt; kt++) {
        const int cur = kt & 1;
        const __half* Kc = smh + cur * BUF_HALVES;
        const __half* Vc = Kc + BN * KSTRH;

        CP_WAIT0();
        __syncthreads();

        if (kt < qt) stage(kt + 1, cur ^ 1);

        // ---- GEMM1: 2 x LDS.128 B-frags per n-tile ----
        float s[8][4];
        #pragma unroll
        for (int nt = 0; nt < 8; nt++) {
            s[nt][0] = 0.f; s[nt][1] = 0.f; s[nt][2] = 0.f; s[nt][3] = 0.f;
            const __half* kb = Kc + (g + 8 * nt) * KSTRH + 16 * t4;
            uint4 lo = *(const uint4*)kb;
            uint4 hi = *(const uint4*)(kb + 8);
            mma_f16(s[nt], qa[0][0], qa[0][1], qa[0][2], qa[0][3], lo.x, lo.y);
            mma_f16(s[nt], qa[1][0], qa[1][1], qa[1][2], qa[1][3], lo.z, lo.w);
            mma_f16(s[nt], qa[2][0], qa[2][1], qa[2][2], qa[2][3], hi.x, hi.y);
            mma_f16(s[nt], qa[3][0], qa[3][1], qa[3][2], qa[3][3], hi.z, hi.w);
        }

        // ---- Causal mask (diagonal tile only), log2 domain ----
        if (kt == qt) {
            const int colb = (kt << 6) + 2 * t4;
            #pragma unroll
            for (int nt = 0; nt < 8; nt++) {
                int c0 = colb + 8 * nt, c1 = c0 + 1;
                if (c0 > row0) s[nt][0] = MASKVAL;
                if (c1 > row0) s[nt][1] = MASKVAL;
                if (c0 > row1) s[nt][2] = MASKVAL;
                if (c1 > row1) s[nt][3] = MASKVAL;
            }
        }

        // ---- Online softmax in log2 domain (tree reductions); P packed in regs ----
        float a0r[8], a1r[8];
        #pragma unroll
        for (int nt = 0; nt < 8; nt++) {
            a0r[nt] = fmaxf(s[nt][0], s[nt][1]);
            a1r[nt] = fmaxf(s[nt][2], s[nt][3]);
        }
        #pragma unroll
        for (int st = 4; st >= 1; st >>= 1)
            #pragma unroll
            for (int i = 0; i < st; i++) {
                a0r[i] = fmaxf(a0r[i], a0r[i + st]);
                a1r[i] = fmaxf(a1r[i], a1r[i + st]);
            }
        float mx0 = a0r[0], mx1 = a1r[0];
        mx0 = fmaxf(mx0, __shfl_xor_sync(0xffffffffu, mx0, 1));
        mx0 = fmaxf(mx0, __shfl_xor_sync(0xffffffffu, mx0, 2));
        mx1 = fmaxf(mx1, __shfl_xor_sync(0xffffffffu, mx1, 1));
        mx1 = fmaxf(mx1, __shfl_xor_sync(0xffffffffu, mx1, 2));

        float mn0 = fmaxf(m0, mx0), mn1 = fmaxf(m1, mx1);
        float cr0 = ex2(m0 - mn0), cr1 = ex2(m1 - mn1);

        unsigned ph[8][2];
        #pragma unroll
        for (int nt = 0; nt < 8; nt++) {
            float p0 = ex2(s[nt][0] - mn0);
            float p1 = ex2(s[nt][1] - mn0);
            float p2 = ex2(s[nt][2] - mn1);
            float p3 = ex2(s[nt][3] - mn1);
            a0r[nt] = p0 + p1;
            a1r[nt] = p2 + p3;
            ph[nt][0] = packh2(p0, p1);
            ph[nt][1] = packh2(p2, p3);
        }
        #pragma unroll
        for (int st = 4; st >= 1; st >>= 1)
            #pragma unroll
            for (int i = 0; i < st; i++) {
                a0r[i] += a0r[i + st];
                a1r[i] += a1r[i + st];
            }
        float sum0 = a0r[0], sum1 = a1r[0];
        sum0 += __shfl_xor_sync(0xffffffffu, sum0, 1);
        sum0 += __shfl_xor_sync(0xffffffffu, sum0, 2);
        sum1 += __shfl_xor_sync(0xffffffffu, sum1, 1);
        sum1 += __shfl_xor_sync(0xffffffffu, sum1, 2);

        l0 = l0 * cr0 + sum0;
        l1 = l1 * cr1 + sum1;
        m0 = mn0; m1 = mn1;

        #pragma unroll
        for (int nt = 0; nt < 8; nt++) {
            o[nt][0] *= cr0; o[nt][1] *= cr0;
            o[nt][2] *= cr1; o[nt][3] *= cr1;
        }

        // ---- GEMM2: 2 x LDS.128 B-frags per n-tile (doubly-permuted Vt) ----
        #pragma unroll
        for (int nt = 0; nt < 8; nt++) {
            const __half* vp = Vc + (g + 8 * nt) * VTSTRH + 16 * t4;
            uint4 lo = *(const uint4*)vp;
            uint4 hi = *(const uint4*)(vp + 8);
            mma_f16(o[nt], ph[0][0], ph[0][1], ph[1][0], ph[1][1], lo.x, lo.y);
            mma_f16(o[nt], ph[2][0], ph[2][1], ph[3][0], ph[3][1], lo.z, lo.w);
            mma_f16(o[nt], ph[4][0], ph[4][1], ph[5][0], ph[5][1], hi.x, hi.y);
            mma_f16(o[nt], ph[6][0], ph[6][1], ph[7][0], ph[7][1], hi.z, hi.w);
        }
    }

    // ---- Epilogue ----
    const float inv0 = 1.f / l0;
    const float inv1 = 1.f / l1;
    float* Op0 = Out + ((size_t)b * S_LEN + row0) * (NHEAD * DHEAD) + h * DHEAD;
    float* Op1 = Out + ((size_t)b * S_LEN + row1) * (NHEAD * DHEAD) + h * DHEAD;
    #pragma unroll
    for (int nt = 0; nt < 8; nt++) {
        int col = 8 * nt + 2 * t4;
        *(float2*)(Op0 + col) = make_float2(o[nt][0] * inv0, o[nt][1] * inv0);
        *(float2*)(Op1 + col) = make_float2(o[nt][2] * inv1, o[nt][3] * inv1);
    }
}

extern "C" void kernel_launch(void* const* d_in, const int* in_sizes, int n_in,
                              void* d_out, int out_size) {
    (void)in_sizes; (void)n_in; (void)out_size;
    const float* q = (const float*)d_in[0];
    const float* k = (const float*)d_in[1];
    const float* v = (const float*)d_in[2];
    float* out = (float*)d_out;

    dim3 pgrid(S_LEN / 64, 4 * NHEAD);
    prep_kernel<<<pgrid, 128>>>(k, v);

    const int smem_bytes = 2 * BUF_HALVES * (int)sizeof(__half);   // 36864 B
    cudaFuncSetAttribute(attn_tc10_kernel,
                         cudaFuncAttributeMaxDynamicSharedMemorySize, smem_bytes);
    dim3 grid(S_LEN / BM, 4 * NHEAD);   // (32, 64)
    attn_tc10_kernel<<<grid, 128, smem_bytes>>>(q, out);
}

// round 16
// speedup vs baseline: 1.1447x; 1.1188x over previous
#include <cuda_runtime.h>
#include <cuda_fp16.h>

#define S_LEN 2048
#define NHEAD 16
#define DHEAD 64
#define BM 64
#define BN 64
#define KSTRH 80    // K smem stride (halves): conflict-free LDS.64 B-frags
#define VTSTRH 80   // Vt smem stride (halves)
#define BUF_HALVES (BN * KSTRH + DHEAD * VTSTRH)

#define QSCALE 0.18033688011112042f    /* 0.125 * log2(e) */
#define MASKVAL (-14426.950408889634f) /* -10000 * log2(e) */

// fp16 scratch — __device__ globals, no allocation
__device__ __half g_Kh[(size_t)4 * NHEAD * S_LEN * DHEAD];
__device__ __half g_Vt[(size_t)4 * NHEAD * DHEAD * S_LEN];  // [bh][d][key], keys permuted per 16-chunk

static __device__ __forceinline__ unsigned packh2(float lo, float hi) {
    __half2 h = __floats2half2_rn(lo, hi);
    return *(unsigned*)&h;
}

static __device__ __forceinline__ float ex2(float x) {
    float y;
    asm("ex2.approx.ftz.f32 %0, %1;" : "=f"(y) : "f"(x));
    return y;
}

// two fp16 exponentials in ONE MUFU op — the MUFU-pressure fix
static __device__ __forceinline__ unsigned ex2h2(unsigned x) {
    unsigned y;
    asm("ex2.approx.f16x2 %0, %1;" : "=r"(y) : "r"(x));
    return y;
}

static __device__ __forceinline__ void mma_f16(float* d,
                                               unsigned a0, unsigned a1, unsigned a2, unsigned a3,
                                               unsigned b0, unsigned b1) {
    asm volatile("mma.sync.aligned.m16n8k16.row.col.f32.f16.f16.f32 "
                 "{%0,%1,%2,%3}, {%4,%5,%6,%7}, {%8,%9}, {%0,%1,%2,%3};"
                 : "+f"(d[0]), "+f"(d[1]), "+f"(d[2]), "+f"(d[3])
                 : "r"(a0), "r"(a1), "r"(a2), "r"(a3), "r"(b0), "r"(b1));
}

#define CP_ASYNC16(dst_u32, src_ptr) \
    asm volatile("cp.async.cg.shared.global [%0], [%1], 16;" :: "r"(dst_u32), "l"(src_ptr))
#define CP_COMMIT() asm volatile("cp.async.commit_group;" ::: "memory")
#define CP_WAIT0()  asm volatile("cp.async.wait_group 0;" ::: "memory")

// ---- Pre-pass: K -> fp16 (natural layout), V -> fp16 transposed+key-permuted ----
__global__ __launch_bounds__(128)
void prep_kernel(const float* __restrict__ K, const float* __restrict__ V) {
    const int kt  = blockIdx.x;
    const int bh  = blockIdx.y;
    const int tid = threadIdx.x;

    const float* Kg = K + ((size_t)bh * S_LEN + (size_t)kt * 64) * DHEAD;
    const float* Vg = V + ((size_t)bh * S_LEN + (size_t)kt * 64) * DHEAD;
    __half* Kh = g_Kh + ((size_t)bh * S_LEN + (size_t)kt * 64) * DHEAD;

    #pragma unroll
    for (int it = 0; it < 8; it++) {
        int i  = tid + (it << 7);
        int r  = i >> 4;
        int d4 = (i & 15) << 2;
        float4 kk = *(const float4*)(Kg + r * DHEAD + d4);
        __half2* dst = (__half2*)(Kh + r * DHEAD + d4);
        dst[0] = __floats2half2_rn(kk.x, kk.y);
        dst[1] = __floats2half2_rn(kk.z, kk.w);
    }

    // V transpose with within-16 key permutation: pos 4j+r <- key 2j+r ; pos 4j+2+r <- key 8+2j+r
    const int v_rp = tid & 15;
    const int v_h  = tid >> 4;
    #pragma unroll
    for (int u = 0; u < 2; u++)
        #pragma unroll
        for (int kh = 0; kh < 2; kh++) {
            int key = 2 * (v_rp + 16 * kh);
            int w   = key & 15;
            int pos = (key & ~15) + 4 * ((w & 7) >> 1) + ((w < 8) ? 0 : 2);
            int dv  = 4 * v_h + 32 * u;
            const float* vp = Vg + key * DHEAD + dv;
            float4 v0 = *(const float4*)vp;
            float4 v1 = *(const float4*)(vp + DHEAD);
            __half* Vt = g_Vt + (size_t)bh * DHEAD * S_LEN + (size_t)kt * 64 + pos;
            *(__half2*)(Vt + (size_t)(dv + 0) * S_LEN) = __floats2half2_rn(v0.x, v1.x);
            *(__half2*)(Vt + (size_t)(dv + 1) * S_LEN) = __floats2half2_rn(v0.y, v1.y);
            *(__half2*)(Vt + (size_t)(dv + 2) * S_LEN) = __floats2half2_rn(v0.z, v1.z);
            *(__half2*)(Vt + (size_t)(dv + 3) * S_LEN) = __floats2half2_rn(v0.w, v1.w);
        }
}

__global__ __launch_bounds__(128, 5)
void attn_tc11_kernel(const float* __restrict__ Q, float* __restrict__ Out) {
    extern __shared__ __half smh[];
    const unsigned smem_b = (unsigned)__cvta_generic_to_shared(smh);

    const int qt   = (gridDim.x - 1) - blockIdx.x;   // heavy tiles first
    const int bh   = blockIdx.y;
    const int b    = bh >> 4;
    const int h    = bh & 15;
    const int qrow = qt * BM;

    const int tid  = threadIdx.x;
    const int warp = tid >> 5;
    const int lane = tid & 31;
    const int g    = lane >> 2;
    const int t4   = lane & 3;
    const int r0w  = warp << 4;
    const int row0 = qrow + r0w + g;
    const int row1 = row0 + 8;

    const char* KhB = (const char*)(g_Kh + (size_t)bh * S_LEN * DHEAD);
    const char* VtB = (const char*)(g_Vt + (size_t)bh * DHEAD * S_LEN);

    // ---- Q A-fragments: k-map k=2t4 <-> d=16ks+4t4 (+1,+2,+3) ----
    unsigned qa[4][4];
    {
        const float* Qg = Q + ((size_t)bh * S_LEN + qrow + r0w) * DHEAD;
        #pragma unroll
        for (int ks = 0; ks < 4; ks++) {
            const float* rp = Qg + g * DHEAD + 16 * ks + 4 * t4;
            float4 x = *(const float4*)rp;
            float4 y = *(const float4*)(rp + 8 * DHEAD);
            qa[ks][0] = packh2(QSCALE * x.x, QSCALE * x.y);
            qa[ks][1] = packh2(QSCALE * y.x, QSCALE * y.y);
            qa[ks][2] = packh2(QSCALE * x.z, QSCALE * x.w);
            qa[ks][3] = packh2(QSCALE * y.z, QSCALE * y.w);
        }
    }

    float o[8][4];
    #pragma unroll
    for (int nt = 0; nt < 8; nt++)
        #pragma unroll
        for (int e = 0; e < 4; e++) o[nt][e] = 0.f;

    float m0 = -1e30f, m1 = -1e30f, l0 = 0.f, l1 = 0.f;

    auto stage = [&](int kt, int slot) {
        unsigned sb = smem_b + (unsigned)slot * (BUF_HALVES * 2);
        const char* Ksrc = KhB + (size_t)kt * BN * DHEAD * 2;
        #pragma unroll
        for (int it = 0; it < 4; it++) {
            int c = tid + (it << 7);
            unsigned dst = sb + (unsigned)(c >> 3) * (KSTRH * 2) + (unsigned)(c & 7) * 16;
            CP_ASYNC16(dst, Ksrc + (size_t)c * 16);
        }
        const char* Vsrc = VtB + (size_t)kt * BN * 2;
        unsigned vb = sb + BN * KSTRH * 2;
        #pragma unroll
        for (int it = 0; it < 4; it++) {
            int c = tid + (it << 7);
            int r = c >> 3;
            unsigned dst = vb + (unsigned)r * (VTSTRH * 2) + (unsigned)(c & 7) * 16;
            CP_ASYNC16(dst, Vsrc + (size_t)r * (S_LEN * 2) + (size_t)(c & 7) * 16);
        }
        CP_COMMIT();
    };

    stage(0, 0);

    for (int kt = 0; kt <= qt; kt++) {
        const int cur = kt & 1;
        const __half* Kc = smh + cur * BUF_HALVES;
        const __half* Vc = Kc + BN * KSTRH;

        CP_WAIT0();
        __syncthreads();

        if (kt < qt) stage(kt + 1, cur ^ 1);

        // ---- GEMM1: one LDS.64 B-frag per MMA ----
        float s[8][4];
        #pragma unroll
        for (int nt = 0; nt < 8; nt++) {
            s[nt][0] = 0.f; s[nt][1] = 0.f; s[nt][2] = 0.f; s[nt][3] = 0.f;
            const __half* kb = Kc + (g + 8 * nt) * KSTRH + 4 * t4;
            #pragma unroll
            for (int ks = 0; ks < 4; ks++) {
                uint2 bb = *(const uint2*)(kb + 16 * ks);
                mma_f16(s[nt], qa[ks][0], qa[ks][1], qa[ks][2], qa[ks][3], bb.x, bb.y);
            }
        }

        // ---- Causal mask (diagonal tile only), log2 domain ----
        if (kt == qt) {
            const int colb = (kt << 6) + 2 * t4;
            #pragma unroll
            for (int nt = 0; nt < 8; nt++) {
                int c0 = colb + 8 * nt, c1 = c0 + 1;
                if (c0 > row0) s[nt][0] = MASKVAL;
                if (c1 > row0) s[nt][1] = MASKVAL;
                if (c0 > row1) s[nt][2] = MASKVAL;
                if (c1 > row1) s[nt][3] = MASKVAL;
            }
        }

        // ---- Online softmax: tree max, then f16x2 exponentials (1 MUFU per 2 p's) ----
        float a0r[8], a1r[8];
        #pragma unroll
        for (int nt = 0; nt < 8; nt++) {
            a0r[nt] = fmaxf(s[nt][0], s[nt][1]);
            a1r[nt] = fmaxf(s[nt][2], s[nt][3]);
        }
        #pragma unroll
        for (int st = 4; st >= 1; st >>= 1)
            #pragma unroll
            for (int i = 0; i < st; i++) {
                a0r[i] = fmaxf(a0r[i], a0r[i + st]);
                a1r[i] = fmaxf(a1r[i], a1r[i + st]);
            }
        float mx0 = a0r[0], mx1 = a1r[0];
        mx0 = fmaxf(mx0, __shfl_xor_sync(0xffffffffu, mx0, 1));
        mx0 = fmaxf(mx0, __shfl_xor_sync(0xffffffffu, mx0, 2));
        mx1 = fmaxf(mx1, __shfl_xor_sync(0xffffffffu, mx1, 1));
        mx1 = fmaxf(mx1, __shfl_xor_sync(0xffffffffu, mx1, 2));

        float mn0 = fmaxf(m0, mx0), mn1 = fmaxf(m1, mx1);
        float cr0 = ex2(m0 - mn0), cr1 = ex2(m1 - mn1);

        unsigned ph[8][2];
        #pragma unroll
        for (int nt = 0; nt < 8; nt++) {
            // pack (s - mn) to half2, exponentiate two at a time in one MUFU op
            ph[nt][0] = ex2h2(packh2(s[nt][0] - mn0, s[nt][1] - mn0));
            ph[nt][1] = ex2h2(packh2(s[nt][2] - mn1, s[nt][3] - mn1));
            // fp32 row-sum of the EXACT fp16 p's used in GEMM2
            float2 f0 = __half22float2(*(__half2*)&ph[nt][0]);
            float2 f1 = __half22float2(*(__half2*)&ph[nt][1]);
            a0r[nt] = f0.x + f0.y;
            a1r[nt] = f1.x + f1.y;
        }
        #pragma unroll
        for (int st = 4; st >= 1; st >>= 1)
            #pragma unroll
            for (int i = 0; i < st; i++) {
                a0r[i] += a0r[i + st];
                a1r[i] += a1r[i + st];
            }
        float sum0 = a0r[0], sum1 = a1r[0];
        sum0 += __shfl_xor_sync(0xffffffffu, sum0, 1);
        sum0 += __shfl_xor_sync(0xffffffffu, sum0, 2);
        sum1 += __shfl_xor_sync(0xffffffffu, sum1, 1);
        sum1 += __shfl_xor_sync(0xffffffffu, sum1, 2);

        l0 = l0 * cr0 + sum0;
        l1 = l1 * cr1 + sum1;
        m0 = mn0; m1 = mn1;

        #pragma unroll
        for (int nt = 0; nt < 8; nt++) {
            o[nt][0] *= cr0; o[nt][1] *= cr0;
            o[nt][2] *= cr1; o[nt][3] *= cr1;
        }

        // ---- GEMM2: one LDS.64 B-frag per MMA (key-permuted Vt) ----
        #pragma unroll
        for (int ks = 0; ks < 4; ks++) {
            unsigned pa0 = ph[2 * ks][0];
            unsigned pa1 = ph[2 * ks][1];
            unsigned pa2 = ph[2 * ks + 1][0];
            unsigned pa3 = ph[2 * ks + 1][1];
            const __half* vb = Vc + 16 * ks + 4 * t4;
            #pragma unroll
            for (int nt = 0; nt < 8; nt++) {
                uint2 bb = *(const uint2*)(vb + (g + 8 * nt) * VTSTRH);
                mma_f16(o[nt], pa0, pa1, pa2, pa3, bb.x, bb.y);
            }
        }
    }

    // ---- Epilogue ----
    const float inv0 = 1.f / l0;
    const float inv1 = 1.f / l1;
    float* Op0 = Out + ((size_t)b * S_LEN + row0) * (NHEAD * DHEAD) + h * DHEAD;
    float* Op1 = Out + ((size_t)b * S_LEN + row1) * (NHEAD * DHEAD) + h * DHEAD;
    #pragma unroll
    for (int nt = 0; nt < 8; nt++) {
        int col = 8 * nt + 2 * t4;
        *(float2*)(Op0 + col) = make_float2(o[nt][0] * inv0, o[nt][1] * inv0);
        *(float2*)(Op1 + col) = make_float2(o[nt][2] * inv1, o[nt][3] * inv1);
    }
}

extern "C" void kernel_launch(void* const* d_in, const int* in_sizes, int n_in,
                              void* d_out, int out_size) {
    (void)in_sizes; (void)n_in; (void)out_size;
    const float* q = (const float*)d_in[0];
    const float* k = (const float*)d_in[1];
    const float* v = (const float*)d_in[2];
    float* out = (float*)d_out;

    dim3 pgrid(S_LEN / 64, 4 * NHEAD);
    prep_kernel<<<pgrid, 128>>>(k, v);

    const int smem_bytes = 2 * BUF_HALVES * (int)sizeof(__half);   // 40960 B
    cudaFuncSetAttribute(attn_tc11_kernel,
                         cudaFuncAttributeMaxDynamicSharedMemorySize, smem_bytes);
    dim3 grid(S_LEN / BM, 4 * NHEAD);   // (32, 64)
    attn_tc11_kernel<<<grid, 128, smem_bytes>>>(q, out);
}

// round 17
// speedup vs baseline: 1.1841x; 1.0344x over previous
#include <cuda_runtime.h>
#include <cuda_fp16.h>

#define S_LEN 2048
#define NHEAD 16
#define DHEAD 64
#define BM 64
#define BN 64
#define SLOT_HALVES 8192          /* K tile 4096 halves + V tile 4096 halves */
#define SLOT_BYTES  16384

#define QSCALE 0.18033688011112042f    /* 0.125 * log2(e) */
#define MASKVAL (-14426.950408889634f) /* -10000 * log2(e) */

// fp16 scratch — __device__ globals, no allocation
__device__ __half g_Kh[(size_t)4 * NHEAD * S_LEN * DHEAD];
__device__ __half g_Vt[(size_t)4 * NHEAD * DHEAD * S_LEN];  // [bh][d][key], keys permuted per 16-chunk

static __device__ __forceinline__ unsigned packh2(float lo, float hi) {
    __half2 h = __floats2half2_rn(lo, hi);
    return *(unsigned*)&h;
}

static __device__ __forceinline__ float ex2(float x) {
    float y;
    asm("ex2.approx.ftz.f32 %0, %1;" : "=f"(y) : "f"(x));
    return y;
}

static __device__ __forceinline__ unsigned ex2h2(unsigned x) {
    unsigned y;
    asm("ex2.approx.f16x2 %0, %1;" : "=r"(y) : "r"(x));
    return y;
}

static __device__ __forceinline__ void mma_f16(float* d,
                                               unsigned a0, unsigned a1, unsigned a2, unsigned a3,
                                               unsigned b0, unsigned b1) {
    asm volatile("mma.sync.aligned.m16n8k16.row.col.f32.f16.f16.f32 "
                 "{%0,%1,%2,%3}, {%4,%5,%6,%7}, {%8,%9}, {%0,%1,%2,%3};"
                 : "+f"(d[0]), "+f"(d[1]), "+f"(d[2]), "+f"(d[3])
                 : "r"(a0), "r"(a1), "r"(a2), "r"(a3), "r"(b0), "r"(b1));
}

#define CP_ASYNC16(dst_u32, src_ptr) \
    asm volatile("cp.async.cg.shared.global [%0], [%1], 16;" :: "r"(dst_u32), "l"(src_ptr))
#define CP_COMMIT() asm volatile("cp.async.commit_group;" ::: "memory")
#define CP_WAIT0()  asm volatile("cp.async.wait_group 0;" ::: "memory")
#define CP_WAIT1()  asm volatile("cp.async.wait_group 1;" ::: "memory")

// ---- Pre-pass: K -> fp16 (natural layout), V -> fp16 transposed+key-permuted ----
__global__ __launch_bounds__(128)
void prep_kernel(const float* __restrict__ K, const float* __restrict__ V) {
    const int kt  = blockIdx.x;
    const int bh  = blockIdx.y;
    const int tid = threadIdx.x;

    const float* Kg = K + ((size_t)bh * S_LEN + (size_t)kt * 64) * DHEAD;
    const float* Vg = V + ((size_t)bh * S_LEN + (size_t)kt * 64) * DHEAD;
    __half* Kh = g_Kh + ((size_t)bh * S_LEN + (size_t)kt * 64) * DHEAD;

    #pragma unroll
    for (int it = 0; it < 8; it++) {
        int i  = tid + (it << 7);
        int r  = i >> 4;
        int d4 = (i & 15) << 2;
        float4 kk = *(const float4*)(Kg + r * DHEAD + d4);
        __half2* dst = (__half2*)(Kh + r * DHEAD + d4);
        dst[0] = __floats2half2_rn(kk.x, kk.y);
        dst[1] = __floats2half2_rn(kk.z, kk.w);
    }

    const int v_rp = tid & 15;
    const int v_h  = tid >> 4;
    #pragma unroll
    for (int u = 0; u < 2; u++)
        #pragma unroll
        for (int kh = 0; kh < 2; kh++) {
            int key = 2 * (v_rp + 16 * kh);
            int w   = key & 15;
            int pos = (key & ~15) + 4 * ((w & 7) >> 1) + ((w < 8) ? 0 : 2);
            int dv  = 4 * v_h + 32 * u;
            const float* vp = Vg + key * DHEAD + dv;
            float4 v0 = *(const float4*)vp;
            float4 v1 = *(const float4*)(vp + DHEAD);
            __half* Vt = g_Vt + (size_t)bh * DHEAD * S_LEN + (size_t)kt * 64 + pos;
            *(__half2*)(Vt + (size_t)(dv + 0) * S_LEN) = __floats2half2_rn(v0.x, v1.x);
            *(__half2*)(Vt + (size_t)(dv + 1) * S_LEN) = __floats2half2_rn(v0.y, v1.y);
            *(__half2*)(Vt + (size_t)(dv + 2) * S_LEN) = __floats2half2_rn(v0.z, v1.z);
            *(__half2*)(Vt + (size_t)(dv + 3) * S_LEN) = __floats2half2_rn(v0.w, v1.w);
        }
}

__global__ __launch_bounds__(128, 4)
void attn_tc12_kernel(const float* __restrict__ Q, float* __restrict__ Out) {
    extern __shared__ __half smh[];   // 3 slots x [K: 64x64 swz | Vt: 64x64 swz]
    const unsigned smem_b = (unsigned)__cvta_generic_to_shared(smh);

    const int qt   = (gridDim.x - 1) - blockIdx.x;   // heavy tiles first
    const int bh   = blockIdx.y;
    const int b    = bh >> 4;
    const int h    = bh & 15;
    const int qrow = qt * BM;

    const int tid  = threadIdx.x;
    const int warp = tid >> 5;
    const int lane = tid & 31;
    const int g    = lane >> 2;
    const int t4   = lane & 3;
    const int gm   = g & 3;           // swizzle key
    const int r0w  = warp << 4;
    const int row0 = qrow + r0w + g;
    const int row1 = row0 + 8;

    // per-thread swizzled k-chunk offsets (halves)
    const int ofs0 = 16 * (0 ^ gm) + 4 * t4;
    const int ofs1 = 16 * (1 ^ gm) + 4 * t4;
    const int ofs2 = 16 * (2 ^ gm) + 4 * t4;
    const int ofs3 = 16 * (3 ^ gm) + 4 * t4;

    const char* KhB = (const char*)(g_Kh + (size_t)bh * S_LEN * DHEAD);
    const char* VtB = (const char*)(g_Vt + (size_t)bh * DHEAD * S_LEN);

    // ---- Q A-fragments: k-map k=2t4 <-> d=16ks+4t4 (+1,+2,+3) ----
    unsigned qa[4][4];
    {
        const float* Qg = Q + ((size_t)bh * S_LEN + qrow + r0w) * DHEAD;
        #pragma unroll
        for (int ks = 0; ks < 4; ks++) {
            const float* rp = Qg + g * DHEAD + 16 * ks + 4 * t4;
            float4 x = *(const float4*)rp;
            float4 y = *(const float4*)(rp + 8 * DHEAD);
            qa[ks][0] = packh2(QSCALE * x.x, QSCALE * x.y);
            qa[ks][1] = packh2(QSCALE * y.x, QSCALE * y.y);
            qa[ks][2] = packh2(QSCALE * x.z, QSCALE * x.w);
            qa[ks][3] = packh2(QSCALE * y.z, QSCALE * y.w);
        }
    }

    float o[8][4];
    #pragma unroll
    for (int nt = 0; nt < 8; nt++)
        #pragma unroll
        for (int e = 0; e < 4; e++) o[nt][e] = 0.f;

    float m0 = -1e30f, m1 = -1e30f, l0 = 0.f, l1 = 0.f;
    float s[8][4];
    unsigned ph[8][2];

    // ---- async stage with XOR swizzle (phys chunk = chunk ^ 2*(row&3)) ----
    auto stage = [&](int kt, int slot) {
        unsigned sb = smem_b + (unsigned)slot * SLOT_BYTES;
        const char* Ksrc = KhB + (size_t)kt * 64 * DHEAD * 2;   // 8 KB contiguous
        #pragma unroll
        for (int it = 0; it < 4; it++) {
            int c  = tid + (it << 7);
            int r  = c >> 3, ch = c & 7;
            unsigned dst = sb + (unsigned)r * 128 + (unsigned)((ch ^ (2 * (r & 3))) * 16);
            CP_ASYNC16(dst, Ksrc + (size_t)c * 16);
        }
        const char* Vsrc = VtB + (size_t)kt * 64 * 2;
        unsigned vb = sb + 8192;
        #pragma unroll
        for (int it = 0; it < 4; it++) {
            int c  = tid + (it << 7);
            int r  = c >> 3, ch = c & 7;
            unsigned dst = vb + (unsigned)r * 128 + (unsigned)((ch ^ (2 * (r & 3))) * 16);
            CP_ASYNC16(dst, Vsrc + (size_t)r * (S_LEN * 2) + (size_t)ch * 16);
        }
        CP_COMMIT();
    };

    auto gemm1 = [&](const __half* Kc) {
        #pragma unroll
        for (int nt = 0; nt < 8; nt++) {
            s[nt][0] = 0.f; s[nt][1] = 0.f; s[nt][2] = 0.f; s[nt][3] = 0.f;
            const __half* kb = Kc + (g + 8 * nt) * 64;
            uint2 b0 = *(const uint2*)(kb + ofs0);
            uint2 b1 = *(const uint2*)(kb + ofs1);
            uint2 b2 = *(const uint2*)(kb + ofs2);
            uint2 b3 = *(const uint2*)(kb + ofs3);
            mma_f16(s[nt], qa[0][0], qa[0][1], qa[0][2], qa[0][3], b0.x, b0.y);
            mma_f16(s[nt], qa[1][0], qa[1][1], qa[1][2], qa[1][3], b1.x, b1.y);
            mma_f16(s[nt], qa[2][0], qa[2][1], qa[2][2], qa[2][3], b2.x, b2.y);
            mma_f16(s[nt], qa[3][0], qa[3][1], qa[3][2], qa[3][3], b3.x, b3.y);
        }
    };

    // ---- Prologue: fill pipeline ----
    stage(0, 0);
    if (qt >= 1) { stage(1, 1); CP_WAIT1(); }
    else         { CP_WAIT0(); }
    __syncthreads();
    gemm1(smh);   // scores for tile 0 into s

    const int vofs[4] = {ofs0, ofs1, ofs2, ofs3};

    for (int kt = 0; kt <= qt; kt++) {
        // ---- Causal mask (diagonal tile only) on resident s ----
        if (kt == qt) {
            const int colb = (kt << 6) + 2 * t4;
            #pragma unroll
            for (int nt = 0; nt < 8; nt++) {
                int c0 = colb + 8 * nt, c1 = c0 + 1;
                if (c0 > row0) s[nt][0] = MASKVAL;
                if (c1 > row0) s[nt][1] = MASKVAL;
                if (c0 > row1) s[nt][2] = MASKVAL;
                if (c1 > row1) s[nt][3] = MASKVAL;
            }
        }

        // ---- Online softmax (tree max, f16x2 exp) ----
        float a0r[8], a1r[8];
        #pragma unroll
        for (int nt = 0; nt < 8; nt++) {
            a0r[nt] = fmaxf(s[nt][0], s[nt][1]);
            a1r[nt] = fmaxf(s[nt][2], s[nt][3]);
        }
        #pragma unroll
        for (int st = 4; st >= 1; st >>= 1)
            #pragma unroll
            for (int i = 0; i < st; i++) {
                a0r[i] = fmaxf(a0r[i], a0r[i + st]);
                a1r[i] = fmaxf(a1r[i], a1r[i + st]);
            }
        float mx0 = a0r[0], mx1 = a1r[0];
        mx0 = fmaxf(mx0, __shfl_xor_sync(0xffffffffu, mx0, 1));
        mx0 = fmaxf(mx0, __shfl_xor_sync(0xffffffffu, mx0, 2));
        mx1 = fmaxf(mx1, __shfl_xor_sync(0xffffffffu, mx1, 1));
        mx1 = fmaxf(mx1, __shfl_xor_sync(0xffffffffu, mx1, 2));

        float mn0 = fmaxf(m0, mx0), mn1 = fmaxf(m1, mx1);
        float cr0 = ex2(m0 - mn0), cr1 = ex2(m1 - mn1);

        #pragma unroll
        for (int nt = 0; nt < 8; nt++) {
            ph[nt][0] = ex2h2(packh2(s[nt][0] - mn0, s[nt][1] - mn0));
            ph[nt][1] = ex2h2(packh2(s[nt][2] - mn1, s[nt][3] - mn1));
            float2 f0 = __half22float2(*(__half2*)&ph[nt][0]);
            float2 f1 = __half22float2(*(__half2*)&ph[nt][1]);
            a0r[nt] = f0.x + f0.y;
            a1r[nt] = f1.x + f1.y;
        }
        #pragma unroll
        for (int st = 4; st >= 1; st >>= 1)
            #pragma unroll
            for (int i = 0; i < st; i++) {
                a0r[i] += a0r[i + st];
                a1r[i] += a1r[i + st];
            }
        float sum0 = a0r[0], sum1 = a1r[0];
        sum0 += __shfl_xor_sync(0xffffffffu, sum0, 1);
        sum0 += __shfl_xor_sync(0xffffffffu, sum0, 2);
        sum1 += __shfl_xor_sync(0xffffffffu, sum1, 1);
        sum1 += __shfl_xor_sync(0xffffffffu, sum1, 2);

        l0 = l0 * cr0 + sum0;
        l1 = l1 * cr1 + sum1;
        m0 = mn0; m1 = mn1;

        #pragma unroll
        for (int nt = 0; nt < 8; nt++) {
            o[nt][0] *= cr0; o[nt][1] *= cr0;
            o[nt][2] *= cr1; o[nt][3] *= cr1;
        }

        const __half* Vc = smh + (kt % 3) * SLOT_HALVES + 4096;
        const bool has_next = (kt < qt);

        if (has_next) {
            CP_WAIT0();        // tile kt+1 landed (staged last iteration)
            __syncthreads();   // visible to all; slot (kt+2)%3 readers done
            if (kt + 2 <= qt) stage(kt + 2, (kt + 2) % 3);

            // ---- GEMM2(kt) interleaved with GEMM1(kt+1) ----
            const __half* Kn = smh + ((kt + 1) % 3) * SLOT_HALVES;
            #pragma unroll
            for (int i = 0; i < 4; i++) {
                #pragma unroll
                for (int j = 0; j < 2; j++) {
                    const int nt = 2 * i + j;
                    s[nt][0] = 0.f; s[nt][1] = 0.f; s[nt][2] = 0.f; s[nt][3] = 0.f;
                    const __half* kb = Kn + (g + 8 * nt) * 64;
                    uint2 b0 = *(const uint2*)(kb + ofs0);
                    uint2 b1 = *(const uint2*)(kb + ofs1);
                    uint2 b2 = *(const uint2*)(kb + ofs2);
                    uint2 b3 = *(const uint2*)(kb + ofs3);
                    mma_f16(s[nt], qa[0][0], qa[0][1], qa[0][2], qa[0][3], b0.x, b0.y);
                    mma_f16(s[nt], qa[1][0], qa[1][1], qa[1][2], qa[1][3], b1.x, b1.y);
                    mma_f16(s[nt], qa[2][0], qa[2][1], qa[2][2], qa[2][3], b2.x, b2.y);
                    mma_f16(s[nt], qa[3][0], qa[3][1], qa[3][2], qa[3][3], b3.x, b3.y);
                }
                {   // GEMM2 k-chunk i
                    unsigned pa0 = ph[2 * i][0], pa1 = ph[2 * i][1];
                    unsigned pa2 = ph[2 * i + 1][0], pa3 = ph[2 * i + 1][1];
                    #pragma unroll
                    for (int nt = 0; nt < 8; nt++) {
                        uint2 bb = *(const uint2*)(Vc + (g + 8 * nt) * 64 + vofs[i]);
                        mma_f16(o[nt], pa0, pa1, pa2, pa3, bb.x, bb.y);
                    }
                }
            }
        } else {
            // ---- last tile: plain GEMM2 ----
            #pragma unroll
            for (int i = 0; i < 4; i++) {
                unsigned pa0 = ph[2 * i][0], pa1 = ph[2 * i][1];
                unsigned pa2 = ph[2 * i + 1][0], pa3 = ph[2 * i + 1][1];
                #pragma unroll
                for (int nt = 0; nt < 8; nt++) {
                    uint2 bb = *(const uint2*)(Vc + (g + 8 * nt) * 64 + vofs[i]);
                    mma_f16(o[nt], pa0, pa1, pa2, pa3, bb.x, bb.y);
                }
            }
        }
    }

    // ---- Epilogue ----
    const float inv0 = 1.f / l0;
    const float inv1 = 1.f / l1;
    float* Op0 = Out + ((size_t)b * S_LEN + row0) * (NHEAD * DHEAD) + h * DHEAD;
    float* Op1 = Out + ((size_t)b * S_LEN + row1) * (NHEAD * DHEAD) + h * DHEAD;
    #pragma unroll
    for (int nt = 0; nt < 8; nt++) {
        int col = 8 * nt + 2 * t4;
        *(float2*)(Op0 + col) = make_float2(o[nt][0] * inv0, o[nt][1] * inv0);
        *(float2*)(Op1 + col) = make_float2(o[nt][2] * inv1, o[nt][3] * inv1);
    }
}

extern "C" void kernel_launch(void* const* d_in, const int* in_sizes, int n_in,
                              void* d_out, int out_size) {
    (void)in_sizes; (void)n_in; (void)out_size;
    const float* q = (const float*)d_in[0];
    const float* k = (const float*)d_in[1];
    const float* v = (const float*)d_in[2];
    float* out = (float*)d_out;

    dim3 pgrid(S_LEN / 64, 4 * NHEAD);
    prep_kernel<<<pgrid, 128>>>(k, v);

    const int smem_bytes = 3 * SLOT_BYTES;   // 49152 B
    cudaFuncSetAttribute(attn_tc12_kernel,
                         cudaFuncAttributeMaxDynamicSharedMemorySize, smem_bytes);
    dim3 grid(S_LEN / BM, 4 * NHEAD);   // (32, 64)
    attn_tc12_kernel<<<grid, 128, smem_bytes>>>(q, out);
}